// round 15
// baseline (speedup 1.0000x reference)
#include <cuda_runtime.h>
#include <cuda_fp16.h>
#include <stdint.h>

#define NN 100000
#define NP 100096            // NN padded to multiple of 128 (and 64)
#define NE 600000
#define NG 200
#define NL 5
#define OC 10
#define MAXD 32              // ELL row capacity (in-degree ~Poisson(6); P(>32)~1e-14)
#define NTILES (NP / 64)     // 1564
#define PGRID 592            // 148 SMs x 4 CTAs: persistent grid

#define ALPHA_F 0.1f
#define OMA_F 0.9f
#define BETA_F 0.0077821404f
#define OMB_F (1.0f - BETA_F)
#define BN_EPS_F 1e-5f

#define S32 68               // s_rst row stride in uint32: 64 data + 4 pad (bank-skew 4)

// ---------------- scratch (static device globals; zero-initialized) ----------------
__device__ __half d_Yh[(size_t)NL * NP * 128];    // pre-BN layer outputs Y_0..Y_4 (fp16)
__device__ __half d_feat_h[(size_t)NP * 128];     // feat converted to fp16 (pad rows stay 0)
__device__ uint2  d_wfrag[NL * 4096];             // W in MMA-fragment order [l][kk][nf][lane]
__device__ int2  d_ell[(size_t)NN * MAXD];        // (src, w-bits) pairs per dst row
__device__ int   d_cursor[NN];                    // in-degree counters (zeroed each call)
__device__ int   d_deg_out[NN];
__device__ float d_pooled[(NL + 1) * NG * 128];
__device__ float d_colsum[NL * 128];
__device__ float d_colsumsq[NL * 128];
__device__ int   d_gstart[NG + 1];

// ---------------- setup: zero + W fragment permute + feat->fp16 + graph starts ----------------
__global__ void setup_kernel(const float* __restrict__ gcn_w, const float* __restrict__ feat,
                             const int* __restrict__ gid) {
    int i = blockIdx.x * blockDim.x + threadIdx.x;
    if (i < NN * 32) {
        float4 v = ((const float4*)feat)[i];
        __half2 p0 = __floats2half2_rn(v.x, v.y);
        __half2 p1 = __floats2half2_rn(v.z, v.w);
        uint2 pk;
        pk.x = *(uint32_t*)&p0;
        pk.y = *(uint32_t*)&p1;
        ((uint2*)d_feat_h)[i] = pk;
    }
    if (i < NN) { d_deg_out[i] = 0; d_cursor[i] = 0; }
    if (i < (NL + 1) * NG * 128) d_pooled[i] = 0.f;
    if (i < NL * 128) { d_colsum[i] = 0.f; d_colsumsq[i] = 0.f; }
    // W fragment order: (l, kk, nf, lane) -> uint2 (b0,b1) for mma(kk,nf)
    if (i < NL * 4096) {
        int l = i >> 12;
        int r = i & 4095;
        int kk = r >> 9;            // 0..7
        int nf = (r >> 5) & 15;     // 0..15
        int lane = r & 31;
        int qr = lane >> 2;
        int qc = (lane & 3) * 2;
        int n = nf * 8 + qr;
        int k = kk * 16 + qc;
        const float* Wl = gcn_w + l * 16384;
        __half2 h0 = __floats2half2_rn(Wl[k * 128 + n], Wl[(k + 1) * 128 + n]);
        __half2 h1 = __floats2half2_rn(Wl[(k + 8) * 128 + n], Wl[(k + 9) * 128 + n]);
        uint2 b;
        b.x = *(uint32_t*)&h0;
        b.y = *(uint32_t*)&h1;
        d_wfrag[i] = b;
    }
    if (i < NN) {
        int gc = gid[i];
        int gp = (i == 0) ? -1 : gid[i - 1];
        for (int g = gp + 1; g <= gc; ++g) d_gstart[g] = i;
        if (i == NN - 1)
            for (int g = gc + 1; g <= NG; ++g) d_gstart[g] = NN;
    }
}

__global__ void deg_kernel(const int* __restrict__ src) {
    int e = blockIdx.x * blockDim.x + threadIdx.x;
    if (e < NE) atomicAdd(&d_deg_out[src[e]], 1);
}

__global__ void fill_kernel(const int* __restrict__ src, const int* __restrict__ dst) {
    int e = blockIdx.x * blockDim.x + threadIdx.x;
    if (e < NE) {
        int s = src[e];
        int d = dst[e];
        int p = atomicAdd(&d_cursor[d], 1);
        if (p < MAXD) {
            float w = rsqrtf(fmaxf((float)d_deg_out[s], 1.0f));
            d_ell[(size_t)d * MAXD + p] = make_int2(s, __float_as_int(w));
        }
    }
}

// ---------------- fused layer kernel ----------------
__device__ __forceinline__ void mma_f16v(float c[4], uint32_t a0, uint32_t a1, uint32_t a2,
                                         uint32_t a3, uint32_t b0, uint32_t b1) {
    asm volatile(
        "mma.sync.aligned.m16n8k16.row.col.f32.f16.f16.f32 "
        "{%0,%1,%2,%3}, {%4,%5,%6,%7}, {%8,%9}, {%0,%1,%2,%3};\n"
        : "+f"(c[0]), "+f"(c[1]), "+f"(c[2]), "+f"(c[3])
        : "r"(a0), "r"(a1), "r"(a2), "r"(a3), "r"(b0), "r"(b1));
}

__device__ __forceinline__ float4 load_h16(const __half* hbase, int node, int lane) {
    uint2 raw = *(const uint2*)(hbase + (unsigned)node * 128u + (unsigned)lane * 4u);
    __half2 p0 = *(__half2*)&raw.x;
    __half2 p1 = *(__half2*)&raw.y;
    float2 f0 = __half22float2(p0);
    float2 f1 = __half22float2(p1);
    return make_float4(f0.x, f0.y, f1.x, f1.y);
}

// Persistent: grid = PGRID blocks, each loops over tiles of 64 rows.
// Per tile: ELL preload -> gather (BN+ReLU on the fly) -> f16 MMA -> epilogue.
// Stats accumulate in smem across tiles; flushed once per block at the end.
template <bool BN>
__global__ __launch_bounds__(256, 4) void layer_kernel(const int* __restrict__ gid,
                                                       const float* __restrict__ gcn_b,
                                                       const float* __restrict__ bn_g,
                                                       const float* __restrict__ bn_b,
                                                       int layer) {
    __shared__ int2     s_ell[64 * MAXD];   // 16384 B
    __shared__ uint32_t s_rst[64 * S32];    // 17408 B (fp16 pairs, 64 data + 4 pad u32/row)
    __shared__ float    s_stat[256];        // colsum / colsumsq (accumulated across tiles)
    __shared__ float    s_scale[128];
    __shared__ float    s_shift[128];
    __shared__ int      s_deg[64];
    int tid = threadIdx.x;
    int warp = tid >> 5;
    int lane = tid & 31;

    s_stat[tid] = 0.f;
    if (BN && tid < 128) {
        float mu = d_colsum[(layer - 1) * 128 + tid] * (1.0f / NN);
        float var = d_colsumsq[(layer - 1) * 128 + tid] * (1.0f / NN) - mu * mu;
        float sc = bn_g[(layer - 1) * 128 + tid] * rsqrtf(var + BN_EPS_F);
        s_scale[tid] = sc;
        s_shift[tid] = bn_b[(layer - 1) * 128 + tid] - mu * sc;
    }

    const __half* hb = BN ? (d_Yh + (size_t)(layer - 1) * NP * 128) : d_feat_h;
    __half* Y = d_Yh + (size_t)layer * NP * 128;
    const float* bias = gcn_b + layer * 128;
    const uint2* Wf = d_wfrag + layer * 4096;   // [kk][nf][lane]

    // MMA warp mapping (constant across tiles)
    int r0 = (warp & 3) * 16;       // local row tile
    int cb = (warp >> 2) * 64;      // col half
    int qr = lane >> 2;             // 0..7
    int qc = (lane & 3) * 2;        // 0,2,4,6
    int nf0 = cb >> 3;              // 0 or 8

    for (int tile = blockIdx.x; tile < NTILES; tile += PGRID) {
        int rowbase = tile * 64;

        // ---- cooperative ELL + degree preload (overlaps other warps' prior-tile MMA) ----
        {
            int nrows = min(64, NN - rowbase);
            if (nrows > 0) {
                const int2* eb = d_ell + (size_t)rowbase * MAXD;
                for (int j = tid; j < nrows * MAXD; j += 256) s_ell[j] = eb[j];
                if (tid < nrows) s_deg[tid] = d_cursor[rowbase + tid];
            }
            if (tid >= max(0, NN - rowbase) && tid < 64) s_deg[tid] = 0;
        }
        __syncthreads();

        float4 scv, shv;
        if (BN) {
            scv = ((const float4*)s_scale)[lane];
            shv = ((const float4*)s_shift)[lane];
        }

#define BNR(v)                                                        \
    if (BN) {                                                         \
        v.x = fmaxf(v.x * scv.x + shv.x, 0.f);                        \
        v.y = fmaxf(v.y * scv.y + shv.y, 0.f);                        \
        v.z = fmaxf(v.z * scv.z + shv.z, 0.f);                        \
        v.w = fmaxf(v.w * scv.w + shv.w, 0.f);                        \
    }

        // ---- gather + pooled[layer] accumulation via self-read ----
        int cur_g = -1;
        float4 pacc = make_float4(0.f, 0.f, 0.f, 0.f);
#define PFLUSH()                                                                   \
    if (cur_g >= 0) {                                                              \
        float* dp = d_pooled + ((size_t)layer * NG + cur_g) * 128 + lane * 4;      \
        atomicAdd(dp + 0, pacc.x);                                                 \
        atomicAdd(dp + 1, pacc.y);                                                 \
        atomicAdd(dp + 2, pacc.z);                                                 \
        atomicAdd(dp + 3, pacc.w);                                                 \
    }

        for (int t = 0; t < 8; ++t) {
            int rl = warp * 8 + t;
            int n = rowbase + rl;
            float4 r = make_float4(0.f, 0.f, 0.f, 0.f);
            if (n < NN) {
                int deg = min(s_deg[rl], MAXD);
                float4 acc = make_float4(0.f, 0.f, 0.f, 0.f);
                for (int k0 = 0; k0 < deg; k0 += 8) {
                    int   sIdx[8];
                    float wv[8];
                    float4 v[8];
#pragma unroll
                    for (int k = 0; k < 8; ++k) {
                        int2 e = s_ell[rl * MAXD + k0 + k];   // k0+k <= 31 (in-bounds)
                        sIdx[k] = e.x;
                        wv[k] = __int_as_float(e.y);          // stale for OOB lanes (x0 below)
                    }
#pragma unroll
                    for (int k = 0; k < 8; ++k) {
                        if (k0 + k < deg)
                            v[k] = load_h16(hb, sIdx[k], lane);   // predicated LDG
                        else
                            v[k] = make_float4(0.f, 0.f, 0.f, 0.f);
                    }
#pragma unroll
                    for (int k = 0; k < 8; ++k) {
                        BNR(v[k]);
                        acc.x += wv[k] * v[k].x;
                        acc.y += wv[k] * v[k].y;
                        acc.z += wv[k] * v[k].z;
                        acc.w += wv[k] * v[k].w;
                    }
                }
                float4 hv = load_h16(hb, n, lane);
                BNR(hv);
                // pooled accumulation (rows are sorted by graph id)
                int g = __ldg(&gid[n]);
                if (g != cur_g) {
                    PFLUSH();
                    cur_g = g;
                    pacc = make_float4(0.f, 0.f, 0.f, 0.f);
                }
                pacc.x += hv.x; pacc.y += hv.y; pacc.z += hv.z; pacc.w += hv.w;

                float ni = OMA_F * rsqrtf(fmaxf((float)s_deg[rl], 1.0f));
                r.x = ni * acc.x + ALPHA_F * hv.x;
                r.y = ni * acc.y + ALPHA_F * hv.y;
                r.z = ni * acc.z + ALPHA_F * hv.z;
                r.w = ni * acc.w + ALPHA_F * hv.w;
            }
            // store rst as fp16 pairs
            __half2 h0 = __floats2half2_rn(r.x, r.y);
            __half2 h1 = __floats2half2_rn(r.z, r.w);
            uint2 pk;
            pk.x = *(uint32_t*)&h0;
            pk.y = *(uint32_t*)&h1;
            *(uint2*)&s_rst[rl * S32 + lane * 2] = pk;
        }
        PFLUSH();
#undef PFLUSH
#undef BNR
        __syncthreads();

        // ---- MMA: warp tile = 16 rows x 64 cols; A direct from fp16 smem ----
        float acc[8][4];
#pragma unroll
        for (int nt = 0; nt < 8; ++nt)
#pragma unroll
            for (int j = 0; j < 4; ++j) acc[nt][j] = 0.f;

#pragma unroll
        for (int kk = 0; kk < 8; ++kk) {
            uint32_t a0 = s_rst[(r0 + qr) * S32 + kk * 8 + (qc >> 1)];
            uint32_t a1 = s_rst[(r0 + qr + 8) * S32 + kk * 8 + (qc >> 1)];
            uint32_t a2 = s_rst[(r0 + qr) * S32 + kk * 8 + 4 + (qc >> 1)];
            uint32_t a3 = s_rst[(r0 + qr + 8) * S32 + kk * 8 + 4 + (qc >> 1)];
#pragma unroll
            for (int nt = 0; nt < 8; ++nt) {
                uint2 b = Wf[((kk * 16) + nf0 + nt) * 32 + lane];   // coalesced LDG.64
                mma_f16v(acc[nt], a0, a1, a2, a3, b.x, b.y);
            }
        }

        // ---- epilogue: Y = (1-BETA)*rst + BETA*acc + bias (fp16 store) ; stats -> smem ----
        int row1 = rowbase + r0 + qr;
        int row2 = row1 + 8;

#pragma unroll
        for (int nt = 0; nt < 8; ++nt) {
            int col = cb + nt * 8 + qc;
            float bx = bias[col], by = bias[col + 1];
            float s0 = 0.f, s1 = 0.f, q0 = 0.f, q1 = 0.f;
            if (row1 < NN) {
                uint32_t xr = s_rst[(r0 + qr) * S32 + (col >> 1)];
                float2 x = __half22float2(*(__half2*)&xr);
                float ox = OMB_F * x.x + BETA_F * acc[nt][0] + bx;
                float oy = OMB_F * x.y + BETA_F * acc[nt][1] + by;
                *(__half2*)&Y[(size_t)row1 * 128 + col] = __floats2half2_rn(ox, oy);
                s0 += ox; s1 += oy; q0 += ox * ox; q1 += oy * oy;
            }
            if (row2 < NN) {
                uint32_t xr = s_rst[(r0 + qr + 8) * S32 + (col >> 1)];
                float2 x = __half22float2(*(__half2*)&xr);
                float ox = OMB_F * x.x + BETA_F * acc[nt][2] + bx;
                float oy = OMB_F * x.y + BETA_F * acc[nt][3] + by;
                *(__half2*)&Y[(size_t)row2 * 128 + col] = __floats2half2_rn(ox, oy);
                s0 += ox; s1 += oy; q0 += ox * ox; q1 += oy * oy;
            }
#pragma unroll
            for (int m = 4; m <= 16; m <<= 1) {
                s0 += __shfl_xor_sync(0xffffffffu, s0, m);
                s1 += __shfl_xor_sync(0xffffffffu, s1, m);
                q0 += __shfl_xor_sync(0xffffffffu, q0, m);
                q1 += __shfl_xor_sync(0xffffffffu, q1, m);
            }
            if (lane < 4) {
                atomicAdd(&s_stat[col], s0);
                atomicAdd(&s_stat[col + 1], s1);
                atomicAdd(&s_stat[128 + col], q0);
                atomicAdd(&s_stat[128 + col + 1], q1);
            }
        }
        __syncthreads();   // s_rst reused by next tile's gather
    }

    // one global atomic per (stat, col) per block
    float v = s_stat[tid];
    if (tid < 128)
        atomicAdd(&d_colsum[layer * 128 + tid], v);
    else
        atomicAdd(&d_colsumsq[layer * 128 + tid - 128], v);
}

// ---------------- readout ----------------
__global__ __launch_bounds__(128) void pool_last_kernel(const float* __restrict__ bn_g,
                                                        const float* __restrict__ bn_b) {
    int g = blockIdx.x;
    int d = threadIdx.x;
    float mu = d_colsum[(NL - 1) * 128 + d] * (1.0f / NN);
    float var = d_colsumsq[(NL - 1) * 128 + d] * (1.0f / NN) - mu * mu;
    float sc = bn_g[(NL - 1) * 128 + d] * rsqrtf(var + BN_EPS_F);
    float sh = bn_b[(NL - 1) * 128 + d] - mu * sc;
    const __half* Yh = d_Yh + (size_t)(NL - 1) * NP * 128;
    int s = d_gstart[g], e = d_gstart[g + 1];
    float a0 = 0.f, a1 = 0.f, a2 = 0.f, a3 = 0.f;
    float a4 = 0.f, a5 = 0.f, a6 = 0.f, a7 = 0.f;
    int n = s;
#define PL(idx, aa)                                                    \
    {                                                                  \
        float v = __half2float(Yh[(size_t)(n + idx) * 128 + d]);       \
        aa += fmaxf(v * sc + sh, 0.f);                                 \
    }
    for (; n + 7 < e; n += 8) {
        PL(0, a0) PL(1, a1) PL(2, a2) PL(3, a3)
        PL(4, a4) PL(5, a5) PL(6, a6) PL(7, a7)
    }
    for (; n < e; ++n) PL(0, a0)
#undef PL
    float acc = ((a0 + a1) + (a2 + a3)) + ((a4 + a5) + (a6 + a7));
    d_pooled[(NL * NG + g) * 128 + d] = acc;
}

__global__ __launch_bounds__(128) void score_kernel(const float* __restrict__ lin_w,
                                                    const float* __restrict__ lin_b,
                                                    float* __restrict__ out) {
    int g = blockIdx.x;
    int t = threadIdx.x;
    __shared__ float sc[OC];
    __shared__ float s_lse;
    if (t < OC) {
        float b = 0.f;
        for (int i = 0; i <= NL; ++i) b += lin_b[i * OC + t];
        sc[t] = b;
    }
    __syncthreads();
    float part[OC];
#pragma unroll
    for (int o = 0; o < OC; ++o) part[o] = 0.f;
    for (int i = 0; i <= NL; ++i) {
        float p = d_pooled[(i * NG + g) * 128 + t];
        const float* w = lin_w + i * 128 * OC + t * OC;
#pragma unroll
        for (int o = 0; o < OC; ++o) part[o] += p * w[o];
    }
#pragma unroll
    for (int o = 0; o < OC; ++o) atomicAdd(&sc[o], part[o]);
    __syncthreads();
    if (t == 0) {
        float m = sc[0];
        for (int o = 1; o < OC; ++o) m = fmaxf(m, sc[o]);
        float se = 0.f;
        for (int o = 0; o < OC; ++o) se += expf(sc[o] - m);
        s_lse = logf(se) + m;
    }
    __syncthreads();
    if (t < OC) out[g * OC + t] = sc[t] - s_lse;
}

__global__ void mean_kernel(float* __restrict__ out) {
    int idx = blockIdx.x * blockDim.x + threadIdx.x;
    if (idx >= NG * 128) return;
    int g = idx >> 7;
    int d = idx & 127;
    float s = 0.f;
    for (int i = 1; i <= NL; ++i) s += d_pooled[(i * NG + g) * 128 + d];
    out[NG * OC + idx] = s * 0.2f;
}

// ---------------- launch ----------------
extern "C" void kernel_launch(void* const* d_in, const int* in_sizes, int n_in,
                              void* d_out, int out_size) {
    const float* feat  = (const float*)d_in[0];
    const int*   src   = (const int*)d_in[1];
    const int*   dst   = (const int*)d_in[2];
    const int*   gid   = (const int*)d_in[3];
    const float* gcn_w = (const float*)d_in[4];
    const float* gcn_b = (const float*)d_in[5];
    const float* bn_g  = (const float*)d_in[6];
    const float* bn_b  = (const float*)d_in[7];
    const float* lin_w = (const float*)d_in[8];
    const float* lin_b = (const float*)d_in[9];
    float* out = (float*)d_out;

    const int NB_E = (NE + 255) / 256;             // 2344
    const int NB_S = (NN * 32 + 255) / 256;        // 12500 (covers all setup ranges)

    setup_kernel<<<NB_S, 256>>>(gcn_w, feat, gid);
    deg_kernel<<<NB_E, 256>>>(src);
    fill_kernel<<<NB_E, 256>>>(src, dst);

    for (int l = 0; l < NL; ++l) {
        if (l == 0)
            layer_kernel<false><<<PGRID, 256>>>(gid, gcn_b, bn_g, bn_b, l);
        else
            layer_kernel<true><<<PGRID, 256>>>(gid, gcn_b, bn_g, bn_b, l);
    }

    pool_last_kernel<<<NG, 128>>>(bn_g, bn_b);
    score_kernel<<<NG, 128>>>(lin_w, lin_b, out);
    mean_kernel<<<(NG * 128 + 255) / 256, 256>>>(out);
}

// round 16
// speedup vs baseline: 1.0581x; 1.0581x over previous
#include <cuda_runtime.h>
#include <cuda_fp16.h>
#include <stdint.h>

#define NN 100000
#define NP 100096            // NN padded to multiple of 128 (and 64)
#define NE 600000
#define NG 200
#define NL 5
#define OC 10
#define MAXD 32              // ELL row capacity (in-degree ~Poisson(6); P(>32)~1e-14)

#define ALPHA_F 0.1f
#define OMA_F 0.9f
#define BETA_F 0.0077821404f
#define OMB_F (1.0f - BETA_F)
#define BN_EPS_F 1e-5f

#define S32 68               // s_rst row stride in uint32: 64 data + 4 pad (bank-skew 4)

// ---------------- scratch (static device globals; zero-initialized) ----------------
__device__ __half d_Yh[(size_t)NL * NP * 128];    // pre-BN layer outputs Y_0..Y_4 (fp16)
__device__ __half d_feat_h[(size_t)NP * 128];     // feat converted to fp16 (pad rows stay 0)
__device__ uint2  d_wfrag[NL * 4096];             // W in MMA-fragment order [l][kk][nf][lane]
__device__ int2  d_ell[(size_t)NN * MAXD];        // (src, w-bits) pairs per dst row
__device__ int   d_cursor[NN];                    // in-degree counters (zeroed each call)
__device__ int   d_deg_out[NN];
__device__ float d_pooled[(NL + 1) * NG * 128];
__device__ float d_colsum[NL * 128];
__device__ float d_colsumsq[NL * 128];
__device__ int   d_gstart[NG + 1];

// ---------------- setup: zero + W fragment permute + feat->fp16 + graph starts ----------------
__global__ void setup_kernel(const float* __restrict__ gcn_w, const float* __restrict__ feat,
                             const int* __restrict__ gid) {
    int i = blockIdx.x * blockDim.x + threadIdx.x;
    if (i < NN * 32) {
        float4 v = ((const float4*)feat)[i];
        __half2 p0 = __floats2half2_rn(v.x, v.y);
        __half2 p1 = __floats2half2_rn(v.z, v.w);
        uint2 pk;
        pk.x = *(uint32_t*)&p0;
        pk.y = *(uint32_t*)&p1;
        ((uint2*)d_feat_h)[i] = pk;
    }
    if (i < NN) { d_deg_out[i] = 0; d_cursor[i] = 0; }
    if (i < (NL + 1) * NG * 128) d_pooled[i] = 0.f;
    if (i < NL * 128) { d_colsum[i] = 0.f; d_colsumsq[i] = 0.f; }
    // W fragment order: (l, kk, nf, lane) -> uint2 (b0,b1) for mma(kk,nf)
    if (i < NL * 4096) {
        int l = i >> 12;
        int r = i & 4095;
        int kk = r >> 9;            // 0..7
        int nf = (r >> 5) & 15;     // 0..15
        int lane = r & 31;
        int qr = lane >> 2;
        int qc = (lane & 3) * 2;
        int n = nf * 8 + qr;
        int k = kk * 16 + qc;
        const float* Wl = gcn_w + l * 16384;
        __half2 h0 = __floats2half2_rn(Wl[k * 128 + n], Wl[(k + 1) * 128 + n]);
        __half2 h1 = __floats2half2_rn(Wl[(k + 8) * 128 + n], Wl[(k + 9) * 128 + n]);
        uint2 b;
        b.x = *(uint32_t*)&h0;
        b.y = *(uint32_t*)&h1;
        d_wfrag[i] = b;
    }
    if (i < NN) {
        int gc = gid[i];
        int gp = (i == 0) ? -1 : gid[i - 1];
        for (int g = gp + 1; g <= gc; ++g) d_gstart[g] = i;
        if (i == NN - 1)
            for (int g = gc + 1; g <= NG; ++g) d_gstart[g] = NN;
    }
}

__global__ void deg_kernel(const int* __restrict__ src) {
    int e = blockIdx.x * blockDim.x + threadIdx.x;
    if (e < NE) atomicAdd(&d_deg_out[src[e]], 1);
}

__global__ void fill_kernel(const int* __restrict__ src, const int* __restrict__ dst) {
    int e = blockIdx.x * blockDim.x + threadIdx.x;
    if (e < NE) {
        int s = src[e];
        int d = dst[e];
        int p = atomicAdd(&d_cursor[d], 1);
        if (p < MAXD) {
            float w = rsqrtf(fmaxf((float)d_deg_out[s], 1.0f));
            d_ell[(size_t)d * MAXD + p] = make_int2(s, __float_as_int(w));
        }
    }
}

// ---------------- fused layer kernel ----------------
__device__ __forceinline__ void mma_f16v(float c[4], uint32_t a0, uint32_t a1, uint32_t a2,
                                         uint32_t a3, uint32_t b0, uint32_t b1) {
    asm volatile(
        "mma.sync.aligned.m16n8k16.row.col.f32.f16.f16.f32 "
        "{%0,%1,%2,%3}, {%4,%5,%6,%7}, {%8,%9}, {%0,%1,%2,%3};\n"
        : "+f"(c[0]), "+f"(c[1]), "+f"(c[2]), "+f"(c[3])
        : "r"(a0), "r"(a1), "r"(a2), "r"(a3), "r"(b0), "r"(b1));
}

__device__ __forceinline__ float4 load_h16(const __half* hbase, int node, int lane) {
    uint2 raw = *(const uint2*)(hbase + (unsigned)node * 128u + (unsigned)lane * 4u);
    __half2 p0 = *(__half2*)&raw.x;
    __half2 p1 = *(__half2*)&raw.y;
    float2 f0 = __half22float2(p0);
    float2 f1 = __half22float2(p1);
    return make_float4(f0.x, f0.y, f1.x, f1.y);
}

// One block: 64 rows. ELL pairs preloaded to smem (broadcast reads, no per-row L2 chain).
// rst held fp16 in smem. f16 MMA with fragment-order W. Stats hierarchical.
template <bool BN>
__global__ __launch_bounds__(256, 4) void layer_kernel(const int* __restrict__ gid,
                                                       const float* __restrict__ gcn_b,
                                                       const float* __restrict__ bn_g,
                                                       const float* __restrict__ bn_b,
                                                       int layer) {
    __shared__ int2     s_ell[64 * MAXD];   // 16384 B
    __shared__ uint32_t s_rst[64 * S32];    // 17408 B (fp16 pairs, 64 data + 4 pad u32/row)
    __shared__ float    s_stat[256];        // colsum / colsumsq
    __shared__ float    s_scale[128];
    __shared__ float    s_shift[128];
    __shared__ int      s_deg[64];
    int tid = threadIdx.x;
    int warp = tid >> 5;
    int lane = tid & 31;
    int rowbase = blockIdx.x * 64;

    s_stat[tid] = 0.f;
    if (BN && tid < 128) {
        float mu = d_colsum[(layer - 1) * 128 + tid] * (1.0f / NN);
        float var = d_colsumsq[(layer - 1) * 128 + tid] * (1.0f / NN) - mu * mu;
        float sc = bn_g[(layer - 1) * 128 + tid] * rsqrtf(var + BN_EPS_F);
        s_scale[tid] = sc;
        s_shift[tid] = bn_b[(layer - 1) * 128 + tid] - mu * sc;
    }
    // cooperative ELL + degree preload (coalesced; all loads in flight)
    {
        int nrows = min(64, NN - rowbase);
        const int2* eb = d_ell + (size_t)rowbase * MAXD;
        for (int j = tid; j < nrows * MAXD; j += 256) s_ell[j] = eb[j];
        if (tid < nrows) s_deg[tid] = d_cursor[rowbase + tid];
        if (tid >= nrows && tid < 64) s_deg[tid] = 0;
    }
    __syncthreads();

    const __half* hb = BN ? (d_Yh + (size_t)(layer - 1) * NP * 128) : d_feat_h;

    float4 scv, shv;
    if (BN) {
        scv = ((const float4*)s_scale)[lane];
        shv = ((const float4*)s_shift)[lane];
    }

#define BNR(v)                                                        \
    if (BN) {                                                         \
        v.x = fmaxf(v.x * scv.x + shv.x, 0.f);                        \
        v.y = fmaxf(v.y * scv.y + shv.y, 0.f);                        \
        v.z = fmaxf(v.z * scv.z + shv.z, 0.f);                        \
        v.w = fmaxf(v.w * scv.w + shv.w, 0.f);                        \
    }

    // ---- gather + pooled[layer] accumulation via self-read ----
    int cur_g = -1;
    float4 pacc = make_float4(0.f, 0.f, 0.f, 0.f);
#define PFLUSH()                                                                   \
    if (cur_g >= 0) {                                                              \
        float* dp = d_pooled + ((size_t)layer * NG + cur_g) * 128 + lane * 4;      \
        atomicAdd(dp + 0, pacc.x);                                                 \
        atomicAdd(dp + 1, pacc.y);                                                 \
        atomicAdd(dp + 2, pacc.z);                                                 \
        atomicAdd(dp + 3, pacc.w);                                                 \
    }

    for (int t = 0; t < 8; ++t) {
        int rl = warp * 8 + t;
        int n = rowbase + rl;
        float4 r = make_float4(0.f, 0.f, 0.f, 0.f);
        if (n < NN) {
            int deg = min(s_deg[rl], MAXD);
            float4 acc = make_float4(0.f, 0.f, 0.f, 0.f);
            for (int k0 = 0; k0 < deg; k0 += 8) {
                int   sIdx[8];
                float wv[8];
                float4 v[8];
#pragma unroll
                for (int k = 0; k < 8; ++k) {
                    int2 e = s_ell[rl * MAXD + k0 + k];   // k0+k <= 31: in-bounds
                    sIdx[k] = e.x;
                    wv[k] = __int_as_float(e.y);          // stale for OOB lanes (x0 below)
                }
#pragma unroll
                for (int k = 0; k < 8; ++k) {
                    if (k0 + k < deg)
                        v[k] = load_h16(hb, sIdx[k], lane);   // predicated LDG
                    else
                        v[k] = make_float4(0.f, 0.f, 0.f, 0.f);
                }
#pragma unroll
                for (int k = 0; k < 8; ++k) {
                    BNR(v[k]);
                    acc.x += wv[k] * v[k].x;
                    acc.y += wv[k] * v[k].y;
                    acc.z += wv[k] * v[k].z;
                    acc.w += wv[k] * v[k].w;
                }
            }
            float4 hv = load_h16(hb, n, lane);
            BNR(hv);
            // pooled accumulation (rows are sorted by graph id)
            int g = __ldg(&gid[n]);
            if (g != cur_g) {
                PFLUSH();
                cur_g = g;
                pacc = make_float4(0.f, 0.f, 0.f, 0.f);
            }
            pacc.x += hv.x; pacc.y += hv.y; pacc.z += hv.z; pacc.w += hv.w;

            float ni = OMA_F * rsqrtf(fmaxf((float)s_deg[rl], 1.0f));
            r.x = ni * acc.x + ALPHA_F * hv.x;
            r.y = ni * acc.y + ALPHA_F * hv.y;
            r.z = ni * acc.z + ALPHA_F * hv.z;
            r.w = ni * acc.w + ALPHA_F * hv.w;
        }
        // store rst as fp16 pairs
        __half2 h0 = __floats2half2_rn(r.x, r.y);
        __half2 h1 = __floats2half2_rn(r.z, r.w);
        uint2 pk;
        pk.x = *(uint32_t*)&h0;
        pk.y = *(uint32_t*)&h1;
        *(uint2*)&s_rst[rl * S32 + lane * 2] = pk;
    }
    PFLUSH();
#undef PFLUSH
#undef BNR
    __syncthreads();

    // ---- MMA: warp tile = 16 rows x 64 cols; A direct from fp16 smem ----
    int r0 = (warp & 3) * 16;       // local row tile
    int cb = (warp >> 2) * 64;      // col half
    int qr = lane >> 2;             // 0..7
    int qc = (lane & 3) * 2;        // 0,2,4,6
    const uint2* Wf = d_wfrag + layer * 4096;   // [kk][nf][lane]
    int nf0 = cb >> 3;                          // 0 or 8

    float acc[8][4];
#pragma unroll
    for (int nt = 0; nt < 8; ++nt)
#pragma unroll
        for (int j = 0; j < 4; ++j) acc[nt][j] = 0.f;

#pragma unroll
    for (int kk = 0; kk < 8; ++kk) {
        uint32_t a0 = s_rst[(r0 + qr) * S32 + kk * 8 + (qc >> 1)];
        uint32_t a1 = s_rst[(r0 + qr + 8) * S32 + kk * 8 + (qc >> 1)];
        uint32_t a2 = s_rst[(r0 + qr) * S32 + kk * 8 + 4 + (qc >> 1)];
        uint32_t a3 = s_rst[(r0 + qr + 8) * S32 + kk * 8 + 4 + (qc >> 1)];
#pragma unroll
        for (int nt = 0; nt < 8; ++nt) {
            uint2 b = Wf[((kk * 16) + nf0 + nt) * 32 + lane];   // coalesced LDG.64
            mma_f16v(acc[nt], a0, a1, a2, a3, b.x, b.y);
        }
    }

    // ---- epilogue: Y = (1-BETA)*rst + BETA*acc + bias (fp16 store) ; column stats ----
    __half* Y = d_Yh + (size_t)layer * NP * 128;
    const float* bias = gcn_b + layer * 128;
    int row1 = rowbase + r0 + qr;
    int row2 = row1 + 8;

#pragma unroll
    for (int nt = 0; nt < 8; ++nt) {
        int col = cb + nt * 8 + qc;
        float bx = bias[col], by = bias[col + 1];
        float s0 = 0.f, s1 = 0.f, q0 = 0.f, q1 = 0.f;
        if (row1 < NN) {
            uint32_t xr = s_rst[(r0 + qr) * S32 + (col >> 1)];
            float2 x = __half22float2(*(__half2*)&xr);
            float ox = OMB_F * x.x + BETA_F * acc[nt][0] + bx;
            float oy = OMB_F * x.y + BETA_F * acc[nt][1] + by;
            *(__half2*)&Y[(size_t)row1 * 128 + col] = __floats2half2_rn(ox, oy);
            s0 += ox; s1 += oy; q0 += ox * ox; q1 += oy * oy;
        }
        if (row2 < NN) {
            uint32_t xr = s_rst[(r0 + qr + 8) * S32 + (col >> 1)];
            float2 x = __half22float2(*(__half2*)&xr);
            float ox = OMB_F * x.x + BETA_F * acc[nt][2] + bx;
            float oy = OMB_F * x.y + BETA_F * acc[nt][3] + by;
            *(__half2*)&Y[(size_t)row2 * 128 + col] = __floats2half2_rn(ox, oy);
            s0 += ox; s1 += oy; q0 += ox * ox; q1 += oy * oy;
        }
#pragma unroll
        for (int m = 4; m <= 16; m <<= 1) {
            s0 += __shfl_xor_sync(0xffffffffu, s0, m);
            s1 += __shfl_xor_sync(0xffffffffu, s1, m);
            q0 += __shfl_xor_sync(0xffffffffu, q0, m);
            q1 += __shfl_xor_sync(0xffffffffu, q1, m);
        }
        if (lane < 4) {
            atomicAdd(&s_stat[col], s0);
            atomicAdd(&s_stat[col + 1], s1);
            atomicAdd(&s_stat[128 + col], q0);
            atomicAdd(&s_stat[128 + col + 1], q1);
        }
    }

    __syncthreads();
    float v = s_stat[tid];
    if (tid < 128)
        atomicAdd(&d_colsum[layer * 128 + tid], v);
    else
        atomicAdd(&d_colsumsq[layer * 128 + tid - 128], v);
}

// ---------------- readout ----------------
__global__ __launch_bounds__(128) void pool_last_kernel(const float* __restrict__ bn_g,
                                                        const float* __restrict__ bn_b) {
    int g = blockIdx.x;
    int d = threadIdx.x;
    float mu = d_colsum[(NL - 1) * 128 + d] * (1.0f / NN);
    float var = d_colsumsq[(NL - 1) * 128 + d] * (1.0f / NN) - mu * mu;
    float sc = bn_g[(NL - 1) * 128 + d] * rsqrtf(var + BN_EPS_F);
    float sh = bn_b[(NL - 1) * 128 + d] - mu * sc;
    const __half* Yh = d_Yh + (size_t)(NL - 1) * NP * 128;
    int s = d_gstart[g], e = d_gstart[g + 1];
    float a0 = 0.f, a1 = 0.f, a2 = 0.f, a3 = 0.f;
    float a4 = 0.f, a5 = 0.f, a6 = 0.f, a7 = 0.f;
    int n = s;
#define PL(idx, aa)                                                    \
    {                                                                  \
        float v = __half2float(Yh[(size_t)(n + idx) * 128 + d]);       \
        aa += fmaxf(v * sc + sh, 0.f);                                 \
    }
    for (; n + 7 < e; n += 8) {
        PL(0, a0) PL(1, a1) PL(2, a2) PL(3, a3)
        PL(4, a4) PL(5, a5) PL(6, a6) PL(7, a7)
    }
    for (; n < e; ++n) PL(0, a0)
#undef PL
    float acc = ((a0 + a1) + (a2 + a3)) + ((a4 + a5) + (a6 + a7));
    d_pooled[(NL * NG + g) * 128 + d] = acc;
}

__global__ __launch_bounds__(128) void score_kernel(const float* __restrict__ lin_w,
                                                    const float* __restrict__ lin_b,
                                                    float* __restrict__ out) {
    int g = blockIdx.x;
    int t = threadIdx.x;
    __shared__ float sc[OC];
    __shared__ float s_lse;
    if (t < OC) {
        float b = 0.f;
        for (int i = 0; i <= NL; ++i) b += lin_b[i * OC + t];
        sc[t] = b;
    }
    __syncthreads();
    float part[OC];
#pragma unroll
    for (int o = 0; o < OC; ++o) part[o] = 0.f;
    for (int i = 0; i <= NL; ++i) {
        float p = d_pooled[(i * NG + g) * 128 + t];
        const float* w = lin_w + i * 128 * OC + t * OC;
#pragma unroll
        for (int o = 0; o < OC; ++o) part[o] += p * w[o];
    }
#pragma unroll
    for (int o = 0; o < OC; ++o) atomicAdd(&sc[o], part[o]);
    __syncthreads();
    if (t == 0) {
        float m = sc[0];
        for (int o = 1; o < OC; ++o) m = fmaxf(m, sc[o]);
        float se = 0.f;
        for (int o = 0; o < OC; ++o) se += expf(sc[o] - m);
        s_lse = logf(se) + m;
    }
    __syncthreads();
    if (t < OC) out[g * OC + t] = sc[t] - s_lse;
}

__global__ void mean_kernel(float* __restrict__ out) {
    int idx = blockIdx.x * blockDim.x + threadIdx.x;
    if (idx >= NG * 128) return;
    int g = idx >> 7;
    int d = idx & 127;
    float s = 0.f;
    for (int i = 1; i <= NL; ++i) s += d_pooled[(i * NG + g) * 128 + d];
    out[NG * OC + idx] = s * 0.2f;
}

// ---------------- launch ----------------
extern "C" void kernel_launch(void* const* d_in, const int* in_sizes, int n_in,
                              void* d_out, int out_size) {
    const float* feat  = (const float*)d_in[0];
    const int*   src   = (const int*)d_in[1];
    const int*   dst   = (const int*)d_in[2];
    const int*   gid   = (const int*)d_in[3];
    const float* gcn_w = (const float*)d_in[4];
    const float* gcn_b = (const float*)d_in[5];
    const float* bn_g  = (const float*)d_in[6];
    const float* bn_b  = (const float*)d_in[7];
    const float* lin_w = (const float*)d_in[8];
    const float* lin_b = (const float*)d_in[9];
    float* out = (float*)d_out;

    const int NB_E = (NE + 255) / 256;             // 2344
    const int NB_S = (NN * 32 + 255) / 256;        // 12500 (covers all setup ranges)

    setup_kernel<<<NB_S, 256>>>(gcn_w, feat, gid);
    deg_kernel<<<NB_E, 256>>>(src);
    fill_kernel<<<NB_E, 256>>>(src, dst);

    for (int l = 0; l < NL; ++l) {
        if (l == 0)
            layer_kernel<false><<<NP / 64, 256>>>(gid, gcn_b, bn_g, bn_b, l);
        else
            layer_kernel<true><<<NP / 64, 256>>>(gid, gcn_b, bn_g, bn_b, l);
    }

    pool_last_kernel<<<NG, 128>>>(bn_g, bn_b);
    score_kernel<<<NG, 128>>>(lin_w, lin_b, out);
    mean_kernel<<<(NG * 128 + 255) / 256, 256>>>(out);
}

// round 17
// speedup vs baseline: 1.1639x; 1.1000x over previous
#include <cuda_runtime.h>
#include <cuda_fp16.h>
#include <stdint.h>

#define NN 100000
#define NP 100096            // NN padded to multiple of 128 (and 64)
#define NE 600000
#define NG 200
#define NL 5
#define OC 10
#define MAXD 32              // ELL row capacity (in-degree ~Poisson(6); P(>32)~1e-14)

#define ALPHA_F 0.1f
#define OMA_F 0.9f
#define BETA_F 0.0077821404f
#define OMB_F (1.0f - BETA_F)
#define BN_EPS_F 1e-5f

#define S32 68               // s_rst row stride in uint32: 64 data + 4 pad (bank-skew 4)

// ---------------- scratch (static device globals; zero-initialized) ----------------
__device__ __half d_Yh[(size_t)NL * NP * 128];    // pre-BN layer outputs Y_0..Y_4 (fp16)
__device__ __half d_feat_h[(size_t)NP * 128];     // feat converted to fp16 (pad rows stay 0)
__device__ uint2  d_wfrag[NL * 4096];             // W in MMA-fragment order [l][kk][nf][lane]
__device__ int2  d_ell[(size_t)NN * MAXD];        // (src, w-bits) pairs per dst row
__device__ int   d_cursor[NN];                    // in-degree counters (zeroed each call)
__device__ int   d_deg_out[NN];
__device__ float d_pooled[(NL + 1) * NG * 128];
__device__ float d_colsum[NL * 128];
__device__ float d_colsumsq[NL * 128];
__device__ int   d_gstart[NG + 1];

// ---------------- setup: zero + W fragment permute + feat->fp16 + graph starts ----------------
__global__ void setup_kernel(const float* __restrict__ gcn_w, const float* __restrict__ feat,
                             const int* __restrict__ gid) {
    int i = blockIdx.x * blockDim.x + threadIdx.x;
    if (i < NN * 32) {
        float4 v = ((const float4*)feat)[i];
        __half2 p0 = __floats2half2_rn(v.x, v.y);
        __half2 p1 = __floats2half2_rn(v.z, v.w);
        uint2 pk;
        pk.x = *(uint32_t*)&p0;
        pk.y = *(uint32_t*)&p1;
        ((uint2*)d_feat_h)[i] = pk;
    }
    if (i < NN) { d_deg_out[i] = 0; d_cursor[i] = 0; }
    if (i < (NL + 1) * NG * 128) d_pooled[i] = 0.f;
    if (i < NL * 128) { d_colsum[i] = 0.f; d_colsumsq[i] = 0.f; }
    // W fragment order: (l, kk, nf, lane) -> uint2 (b0,b1) for mma(kk,nf)
    if (i < NL * 4096) {
        int l = i >> 12;
        int r = i & 4095;
        int kk = r >> 9;            // 0..7
        int nf = (r >> 5) & 15;     // 0..15
        int lane = r & 31;
        int qr = lane >> 2;
        int qc = (lane & 3) * 2;
        int n = nf * 8 + qr;
        int k = kk * 16 + qc;
        const float* Wl = gcn_w + l * 16384;
        __half2 h0 = __floats2half2_rn(Wl[k * 128 + n], Wl[(k + 1) * 128 + n]);
        __half2 h1 = __floats2half2_rn(Wl[(k + 8) * 128 + n], Wl[(k + 9) * 128 + n]);
        uint2 b;
        b.x = *(uint32_t*)&h0;
        b.y = *(uint32_t*)&h1;
        d_wfrag[i] = b;
    }
    if (i < NN) {
        int gc = gid[i];
        int gp = (i == 0) ? -1 : gid[i - 1];
        for (int g = gp + 1; g <= gc; ++g) d_gstart[g] = i;
        if (i == NN - 1)
            for (int g = gc + 1; g <= NG; ++g) d_gstart[g] = NN;
    }
}

__global__ void deg_kernel(const int* __restrict__ src) {
    int e = blockIdx.x * blockDim.x + threadIdx.x;
    if (e < NE) atomicAdd(&d_deg_out[src[e]], 1);
}

__global__ void fill_kernel(const int* __restrict__ src, const int* __restrict__ dst) {
    int e = blockIdx.x * blockDim.x + threadIdx.x;
    if (e < NE) {
        int s = src[e];
        int d = dst[e];
        int p = atomicAdd(&d_cursor[d], 1);
        if (p < MAXD) {
            float w = rsqrtf(fmaxf((float)d_deg_out[s], 1.0f));
            d_ell[(size_t)d * MAXD + p] = make_int2(s, __float_as_int(w));
        }
    }
}

// ---------------- fused layer kernel ----------------
__device__ __forceinline__ void mma_f16v(float c[4], uint32_t a0, uint32_t a1, uint32_t a2,
                                         uint32_t a3, uint32_t b0, uint32_t b1) {
    asm volatile(
        "mma.sync.aligned.m16n8k16.row.col.f32.f16.f16.f32 "
        "{%0,%1,%2,%3}, {%4,%5,%6,%7}, {%8,%9}, {%0,%1,%2,%3};\n"
        : "+f"(c[0]), "+f"(c[1]), "+f"(c[2]), "+f"(c[3])
        : "r"(a0), "r"(a1), "r"(a2), "r"(a3), "r"(b0), "r"(b1));
}

__device__ __forceinline__ float4 load_h16(const __half* hbase, int node, int lane) {
    uint2 raw = *(const uint2*)(hbase + (unsigned)node * 128u + (unsigned)lane * 4u);
    __half2 p0 = *(__half2*)&raw.x;
    __half2 p1 = *(__half2*)&raw.y;
    float2 f0 = __half22float2(p0);
    float2 f1 = __half22float2(p1);
    return make_float4(f0.x, f0.y, f1.x, f1.y);
}

// One block: 64 rows. ELL pairs preloaded to smem; gather math in half2 (HFMA2/HMAX2).
// rst held fp16 in smem. f16 MMA with fragment-order W. Stats hierarchical.
template <bool BN>
__global__ __launch_bounds__(256, 4) void layer_kernel(const int* __restrict__ gid,
                                                       const float* __restrict__ gcn_b,
                                                       const float* __restrict__ bn_g,
                                                       const float* __restrict__ bn_b,
                                                       int layer) {
    __shared__ int2     s_ell[64 * MAXD];   // 16384 B
    __shared__ uint32_t s_rst[64 * S32];    // 17408 B (fp16 pairs, 64 data + 4 pad u32/row)
    __shared__ float    s_stat[256];        // colsum / colsumsq
    __shared__ float    s_scale[128];
    __shared__ float    s_shift[128];
    __shared__ int      s_deg[64];
    int tid = threadIdx.x;
    int warp = tid >> 5;
    int lane = tid & 31;
    int rowbase = blockIdx.x * 64;

    s_stat[tid] = 0.f;
    if (BN && tid < 128) {
        float mu = d_colsum[(layer - 1) * 128 + tid] * (1.0f / NN);
        float var = d_colsumsq[(layer - 1) * 128 + tid] * (1.0f / NN) - mu * mu;
        float sc = bn_g[(layer - 1) * 128 + tid] * rsqrtf(var + BN_EPS_F);
        s_scale[tid] = sc;
        s_shift[tid] = bn_b[(layer - 1) * 128 + tid] - mu * sc;
    }
    // cooperative ELL + degree preload (coalesced; all loads in flight)
    {
        int nrows = min(64, NN - rowbase);
        const int2* eb = d_ell + (size_t)rowbase * MAXD;
        for (int j = tid; j < nrows * MAXD; j += 256) s_ell[j] = eb[j];
        if (tid < nrows) s_deg[tid] = d_cursor[rowbase + tid];
        if (tid >= nrows && tid < 64) s_deg[tid] = 0;
    }
    __syncthreads();

    const __half* hb = BN ? (d_Yh + (size_t)(layer - 1) * NP * 128) : d_feat_h;

    float4 scv, shv;                // fp32 (self-read path)
    __half2 sc2a, sc2b, sh2a, sh2b; // half2 (edge path)
    const __half2 zero2 = __floats2half2_rn(0.f, 0.f);
    if (BN) {
        scv = ((const float4*)s_scale)[lane];
        shv = ((const float4*)s_shift)[lane];
        sc2a = __floats2half2_rn(scv.x, scv.y);
        sc2b = __floats2half2_rn(scv.z, scv.w);
        sh2a = __floats2half2_rn(shv.x, shv.y);
        sh2b = __floats2half2_rn(shv.z, shv.w);
    }

#define BNRF(v)                                                       \
    if (BN) {                                                         \
        v.x = fmaxf(v.x * scv.x + shv.x, 0.f);                        \
        v.y = fmaxf(v.y * scv.y + shv.y, 0.f);                        \
        v.z = fmaxf(v.z * scv.z + shv.z, 0.f);                        \
        v.w = fmaxf(v.w * scv.w + shv.w, 0.f);                        \
    }

    // ---- gather + pooled[layer] accumulation via self-read ----
    int cur_g = -1;
    float4 pacc = make_float4(0.f, 0.f, 0.f, 0.f);
#define PFLUSH()                                                                   \
    if (cur_g >= 0) {                                                              \
        float* dp = d_pooled + ((size_t)layer * NG + cur_g) * 128 + lane * 4;      \
        atomicAdd(dp + 0, pacc.x);                                                 \
        atomicAdd(dp + 1, pacc.y);                                                 \
        atomicAdd(dp + 2, pacc.z);                                                 \
        atomicAdd(dp + 3, pacc.w);                                                 \
    }

    for (int t = 0; t < 8; ++t) {
        int rl = warp * 8 + t;
        int n = rowbase + rl;
        float4 r = make_float4(0.f, 0.f, 0.f, 0.f);
        if (n < NN) {
            int deg = min(s_deg[rl], MAXD);
            __half2 accA = zero2, accB = zero2;   // half2 accumulators
            for (int k0 = 0; k0 < deg; k0 += 8) {
                int   sIdx[8];
                float wv[8];
                uint2 raw[8];
#pragma unroll
                for (int k = 0; k < 8; ++k) {
                    int2 e = s_ell[rl * MAXD + k0 + k];   // k0+k <= 31: in-bounds
                    sIdx[k] = e.x;
                    wv[k] = __int_as_float(e.y);          // stale for OOB lanes (x0 below)
                }
#pragma unroll
                for (int k = 0; k < 8; ++k) {
                    if (k0 + k < deg)
                        raw[k] = *(const uint2*)(hb + (unsigned)sIdx[k] * 128u +
                                                 (unsigned)lane * 4u);   // predicated LDG
                    else
                        raw[k] = make_uint2(0u, 0u);
                }
#pragma unroll
                for (int k = 0; k < 8; ++k) {
                    __half2 v0 = *(__half2*)&raw[k].x;
                    __half2 v1 = *(__half2*)&raw[k].y;
                    if (BN) {
                        v0 = __hmax2(__hfma2(v0, sc2a, sh2a), zero2);
                        v1 = __hmax2(__hfma2(v1, sc2b, sh2b), zero2);
                    }
                    __half2 w2 = __float2half2_rn(wv[k]);
                    accA = __hfma2(v0, w2, accA);
                    accB = __hfma2(v1, w2, accB);
                }
            }
            float2 fA = __half22float2(accA);
            float2 fB = __half22float2(accB);
            float4 hv = load_h16(hb, n, lane);
            BNRF(hv);
            // pooled accumulation (rows are sorted by graph id)
            int g = __ldg(&gid[n]);
            if (g != cur_g) {
                PFLUSH();
                cur_g = g;
                pacc = make_float4(0.f, 0.f, 0.f, 0.f);
            }
            pacc.x += hv.x; pacc.y += hv.y; pacc.z += hv.z; pacc.w += hv.w;

            float ni = OMA_F * rsqrtf(fmaxf((float)s_deg[rl], 1.0f));
            r.x = ni * fA.x + ALPHA_F * hv.x;
            r.y = ni * fA.y + ALPHA_F * hv.y;
            r.z = ni * fB.x + ALPHA_F * hv.z;
            r.w = ni * fB.y + ALPHA_F * hv.w;
        }
        // store rst as fp16 pairs
        __half2 h0 = __floats2half2_rn(r.x, r.y);
        __half2 h1 = __floats2half2_rn(r.z, r.w);
        uint2 pk;
        pk.x = *(uint32_t*)&h0;
        pk.y = *(uint32_t*)&h1;
        *(uint2*)&s_rst[rl * S32 + lane * 2] = pk;
    }
    PFLUSH();
#undef PFLUSH
#undef BNRF
    __syncthreads();

    // ---- MMA: warp tile = 16 rows x 64 cols; A direct from fp16 smem ----
    int r0 = (warp & 3) * 16;       // local row tile
    int cb = (warp >> 2) * 64;      // col half
    int qr = lane >> 2;             // 0..7
    int qc = (lane & 3) * 2;        // 0,2,4,6
    const uint2* Wf = d_wfrag + layer * 4096;   // [kk][nf][lane]
    int nf0 = cb >> 3;                          // 0 or 8

    float acc[8][4];
#pragma unroll
    for (int nt = 0; nt < 8; ++nt)
#pragma unroll
        for (int j = 0; j < 4; ++j) acc[nt][j] = 0.f;

#pragma unroll
    for (int kk = 0; kk < 8; ++kk) {
        uint32_t a0 = s_rst[(r0 + qr) * S32 + kk * 8 + (qc >> 1)];
        uint32_t a1 = s_rst[(r0 + qr + 8) * S32 + kk * 8 + (qc >> 1)];
        uint32_t a2 = s_rst[(r0 + qr) * S32 + kk * 8 + 4 + (qc >> 1)];
        uint32_t a3 = s_rst[(r0 + qr + 8) * S32 + kk * 8 + 4 + (qc >> 1)];
#pragma unroll
        for (int nt = 0; nt < 8; ++nt) {
            uint2 b = Wf[((kk * 16) + nf0 + nt) * 32 + lane];   // coalesced LDG.64
            mma_f16v(acc[nt], a0, a1, a2, a3, b.x, b.y);
        }
    }

    // ---- epilogue: Y = (1-BETA)*rst + BETA*acc + bias (fp16 store) ; column stats ----
    __half* Y = d_Yh + (size_t)layer * NP * 128;
    const float* bias = gcn_b + layer * 128;
    int row1 = rowbase + r0 + qr;
    int row2 = row1 + 8;

#pragma unroll
    for (int nt = 0; nt < 8; ++nt) {
        int col = cb + nt * 8 + qc;
        float bx = bias[col], by = bias[col + 1];
        float s0 = 0.f, s1 = 0.f, q0 = 0.f, q1 = 0.f;
        if (row1 < NN) {
            uint32_t xr = s_rst[(r0 + qr) * S32 + (col >> 1)];
            float2 x = __half22float2(*(__half2*)&xr);
            float ox = OMB_F * x.x + BETA_F * acc[nt][0] + bx;
            float oy = OMB_F * x.y + BETA_F * acc[nt][1] + by;
            *(__half2*)&Y[(size_t)row1 * 128 + col] = __floats2half2_rn(ox, oy);
            s0 += ox; s1 += oy; q0 += ox * ox; q1 += oy * oy;
        }
        if (row2 < NN) {
            uint32_t xr = s_rst[(r0 + qr + 8) * S32 + (col >> 1)];
            float2 x = __half22float2(*(__half2*)&xr);
            float ox = OMB_F * x.x + BETA_F * acc[nt][2] + bx;
            float oy = OMB_F * x.y + BETA_F * acc[nt][3] + by;
            *(__half2*)&Y[(size_t)row2 * 128 + col] = __floats2half2_rn(ox, oy);
            s0 += ox; s1 += oy; q0 += ox * ox; q1 += oy * oy;
        }
#pragma unroll
        for (int m = 4; m <= 16; m <<= 1) {
            s0 += __shfl_xor_sync(0xffffffffu, s0, m);
            s1 += __shfl_xor_sync(0xffffffffu, s1, m);
            q0 += __shfl_xor_sync(0xffffffffu, q0, m);
            q1 += __shfl_xor_sync(0xffffffffu, q1, m);
        }
        if (lane < 4) {
            atomicAdd(&s_stat[col], s0);
            atomicAdd(&s_stat[col + 1], s1);
            atomicAdd(&s_stat[128 + col], q0);
            atomicAdd(&s_stat[128 + col + 1], q1);
        }
    }

    __syncthreads();
    float v = s_stat[tid];
    if (tid < 128)
        atomicAdd(&d_colsum[layer * 128 + tid], v);
    else
        atomicAdd(&d_colsumsq[layer * 128 + tid - 128], v);
}

// ---------------- readout ----------------
__global__ __launch_bounds__(128) void pool_last_kernel(const float* __restrict__ bn_g,
                                                        const float* __restrict__ bn_b) {
    int g = blockIdx.x;
    int d = threadIdx.x;
    float mu = d_colsum[(NL - 1) * 128 + d] * (1.0f / NN);
    float var = d_colsumsq[(NL - 1) * 128 + d] * (1.0f / NN) - mu * mu;
    float sc = bn_g[(NL - 1) * 128 + d] * rsqrtf(var + BN_EPS_F);
    float sh = bn_b[(NL - 1) * 128 + d] - mu * sc;
    const __half* Yh = d_Yh + (size_t)(NL - 1) * NP * 128;
    int s = d_gstart[g], e = d_gstart[g + 1];
    float a0 = 0.f, a1 = 0.f, a2 = 0.f, a3 = 0.f;
    float a4 = 0.f, a5 = 0.f, a6 = 0.f, a7 = 0.f;
    int n = s;
#define PL(idx, aa)                                                    \
    {                                                                  \
        float v = __half2float(Yh[(size_t)(n + idx) * 128 + d]);       \
        aa += fmaxf(v * sc + sh, 0.f);                                 \
    }
    for (; n + 7 < e; n += 8) {
        PL(0, a0) PL(1, a1) PL(2, a2) PL(3, a3)
        PL(4, a4) PL(5, a5) PL(6, a6) PL(7, a7)
    }
    for (; n < e; ++n) PL(0, a0)
#undef PL
    float acc = ((a0 + a1) + (a2 + a3)) + ((a4 + a5) + (a6 + a7));
    d_pooled[(NL * NG + g) * 128 + d] = acc;
}

__global__ __launch_bounds__(128) void score_kernel(const float* __restrict__ lin_w,
                                                    const float* __restrict__ lin_b,
                                                    float* __restrict__ out) {
    int g = blockIdx.x;
    int t = threadIdx.x;
    __shared__ float sc[OC];
    __shared__ float s_lse;
    if (t < OC) {
        float b = 0.f;
        for (int i = 0; i <= NL; ++i) b += lin_b[i * OC + t];
        sc[t] = b;
    }
    __syncthreads();
    float part[OC];
#pragma unroll
    for (int o = 0; o < OC; ++o) part[o] = 0.f;
    for (int i = 0; i <= NL; ++i) {
        float p = d_pooled[(i * NG + g) * 128 + t];
        const float* w = lin_w + i * 128 * OC + t * OC;
#pragma unroll
        for (int o = 0; o < OC; ++o) part[o] += p * w[o];
    }
#pragma unroll
    for (int o = 0; o < OC; ++o) atomicAdd(&sc[o], part[o]);
    __syncthreads();
    if (t == 0) {
        float m = sc[0];
        for (int o = 1; o < OC; ++o) m = fmaxf(m, sc[o]);
        float se = 0.f;
        for (int o = 0; o < OC; ++o) se += expf(sc[o] - m);
        s_lse = logf(se) + m;
    }
    __syncthreads();
    if (t < OC) out[g * OC + t] = sc[t] - s_lse;
}

__global__ void mean_kernel(float* __restrict__ out) {
    int idx = blockIdx.x * blockDim.x + threadIdx.x;
    if (idx >= NG * 128) return;
    int g = idx >> 7;
    int d = idx & 127;
    float s = 0.f;
    for (int i = 1; i <= NL; ++i) s += d_pooled[(i * NG + g) * 128 + d];
    out[NG * OC + idx] = s * 0.2f;
}

// ---------------- launch ----------------
extern "C" void kernel_launch(void* const* d_in, const int* in_sizes, int n_in,
                              void* d_out, int out_size) {
    const float* feat  = (const float*)d_in[0];
    const int*   src   = (const int*)d_in[1];
    const int*   dst   = (const int*)d_in[2];
    const int*   gid   = (const int*)d_in[3];
    const float* gcn_w = (const float*)d_in[4];
    const float* gcn_b = (const float*)d_in[5];
    const float* bn_g  = (const float*)d_in[6];
    const float* bn_b  = (const float*)d_in[7];
    const float* lin_w = (const float*)d_in[8];
    const float* lin_b = (const float*)d_in[9];
    float* out = (float*)d_out;

    const int NB_E = (NE + 255) / 256;             // 2344
    const int NB_S = (NN * 32 + 255) / 256;        // 12500 (covers all setup ranges)

    setup_kernel<<<NB_S, 256>>>(gcn_w, feat, gid);
    deg_kernel<<<NB_E, 256>>>(src);
    fill_kernel<<<NB_E, 256>>>(src, dst);

    for (int l = 0; l < NL; ++l) {
        if (l == 0)
            layer_kernel<false><<<NP / 64, 256>>>(gid, gcn_b, bn_g, bn_b, l);
        else
            layer_kernel<true><<<NP / 64, 256>>>(gid, gcn_b, bn_g, bn_b, l);
    }

    pool_last_kernel<<<NG, 128>>>(bn_g, bn_b);
    score_kernel<<<NG, 128>>>(lin_w, lin_b, out);
    mean_kernel<<<(NG * 128 + 255) / 256, 256>>>(out);
}